// round 11
// baseline (speedup 1.0000x reference)
#include <cuda_runtime.h>
#include <cuda_fp16.h>
#include <cstdint>
#include <cstddef>

#define D_DIM 1024
#define ROWS  4096   // B*S

// ------------------------- device scratch -------------------------
__device__ __half g_Vh  [ROWS * D_DIM];     // fp16(value)
__device__ __half g_Aoh [D_DIM * D_DIM];    // fp16(Wo)      [m][k]
__device__ __half g_Bvh [D_DIM * D_DIM];    // fp16(Wv^T)    [n][k]
__device__ __half g_Whi [D_DIM * D_DIM];    // fp16(W = Wo@Wv) [n][k]
__device__ float  g_bias[D_DIM];            // Wo@bv + bo

// ------------------------- helpers -------------------------
__device__ __forceinline__ uint32_t smem_u32(const void* p) {
    uint32_t a;
    asm("{ .reg .u64 t; cvta.to.shared.u64 t, %1; cvt.u32.u64 %0, t; }"
        : "=r"(a) : "l"(p));
    return a;
}

__device__ __forceinline__ void ldmatrix_x4(uint32_t* r, uint32_t addr) {
    asm volatile("ldmatrix.sync.aligned.m8n8.x4.shared.b16 {%0,%1,%2,%3}, [%4];"
                 : "=r"(r[0]), "=r"(r[1]), "=r"(r[2]), "=r"(r[3]) : "r"(addr));
}

__device__ __forceinline__ void mma_f16(float* d, const uint32_t* a,
                                        const uint32_t* b) {
    asm volatile(
        "mma.sync.aligned.m16n8k16.row.col.f32.f16.f16.f32 "
        "{%0,%1,%2,%3}, {%4,%5,%6,%7}, {%8,%9}, {%0,%1,%2,%3};"
        : "+f"(d[0]), "+f"(d[1]), "+f"(d[2]), "+f"(d[3])
        : "r"(a[0]), "r"(a[1]), "r"(a[2]), "r"(a[3]), "r"(b[0]), "r"(b[1]));
}

__device__ __forceinline__ void cp_async16(uint32_t dst, const void* src) {
    asm volatile("cp.async.cg.shared.global [%0], [%1], 16;"
                 :: "r"(dst), "l"(src) : "memory");
}

#define BKK   64
#define PITCH 144                            // 128B payload + 16B pad

// ------------------------- node 1: weight conversions ---------------------
// bid < 1024: Wo row convert + bias GEMV.  bid >= 1024: Wv 32x32 transpose.
__global__ void __launch_bounds__(256)
convert_wb(const float* __restrict__ Wo, const float* __restrict__ bv,
           const float* __restrict__ bo, const float* __restrict__ Wv,
           __half* __restrict__ Aoh, __half* __restrict__ Bvh) {
    __shared__ float sm[33 * 32];
    const int bid = blockIdx.x;
    const int tid = threadIdx.x;

    if (bid < 1024) {
        const int row = bid;
        float4 a = ((const float4*)(Wo + (size_t)row * D_DIM))[tid];
        float4 b = ((const float4*)bv)[tid];
        __half2 h0(__float2half(a.x), __float2half(a.y));
        __half2 h1(__float2half(a.z), __float2half(a.w));
        uint2 pk = {*reinterpret_cast<uint32_t*>(&h0),
                    *reinterpret_cast<uint32_t*>(&h1)};
        ((uint2*)(Aoh + (size_t)row * D_DIM))[tid] = pk;
        float s = a.x * b.x + a.y * b.y + a.z * b.z + a.w * b.w;
        #pragma unroll
        for (int o = 16; o > 0; o >>= 1)
            s += __shfl_down_sync(0xFFFFFFFFu, s, o);
        if ((tid & 31) == 0) sm[tid >> 5] = s;
        __syncthreads();
        if (tid < 8) {
            s = sm[tid];
            #pragma unroll
            for (int o = 4; o > 0; o >>= 1)
                s += __shfl_down_sync(0xFFu, s, o);
            if (tid == 0) g_bias[row] = s + bo[row];
        }
    } else {
        const int t  = bid - 1024;
        const int bx = t & 31, by = t >> 5;
        const int tx = tid & 31, ty = tid >> 5;      // 32 x 8
        const int x = bx * 32 + tx;
        const int y = by * 32;
        #pragma unroll
        for (int j = ty; j < 32; j += 8)
            sm[j * 33 + tx] = Wv[(size_t)(y + j) * D_DIM + x];
        __syncthreads();
        const int ox  = by * 32 + tx;
        const int oyb = bx * 32;
        #pragma unroll
        for (int j = ty; j < 32; j += 8)
            Bvh[(size_t)(oyb + j) * D_DIM + ox] = __float2half(sm[tx * 33 + j]);
    }
}

// ------------------------- node 2: GEMM1 + V convert (one launch) ---------
// bid < 256 : 64x64 tile of W = f16(Wo) @ f16(Wv^T) -> fp16 Whi
// bid >= 256: V fp32->fp16, 1024 float4 per block (128 threads x 8)
__global__ void __launch_bounds__(128)
gemm1_vconv(const __half* __restrict__ Aoh, const __half* __restrict__ Bvh,
            __half* __restrict__ Whi,
            const float* __restrict__ value, uint32_t* __restrict__ Vh) {
    constexpr int BT = 64, WM = 32, WN = 32;
    constexpr int NWX = BT / WN;            // 2
    constexpr int MI = WM / 16, NI = WN / 8, NJ = WN / 16;
    constexpr int TPB = BT * PITCH;
    constexpr int STAGE_B = 2 * TPB;
    constexpr int STAGES = 3;
    constexpr int NT = 128;
    constexpr int CHK = (BT * 8) / NT;      // 4
    constexpr int T = D_DIM / BKK;          // 16

    const int bid = blockIdx.x;
    const int tid = threadIdx.x;

    if (bid >= 256) {
        // ---- V fp32 -> fp16 ----
        const int base = (bid - 256) * 1024 + tid;
        #pragma unroll
        for (int u = 0; u < 8; u++) {
            const int i = base + u * 128;
            float4 x = ((const float4*)value)[i];
            __half2 h0(__float2half(x.x), __float2half(x.y));
            __half2 h1(__float2half(x.z), __float2half(x.w));
            Vh[2 * i]     = *reinterpret_cast<uint32_t*>(&h0);
            Vh[2 * i + 1] = *reinterpret_cast<uint32_t*>(&h1);
        }
        return;
    }

    // ---- GEMM1 tile ----
    extern __shared__ __align__(128) char smem[];
    const uint32_t sbase = smem_u32(smem);

    const int wid = tid >> 5;
    const int lid = tid & 31;
    const int wm  = wid / NWX;
    const int wn  = wid % NWX;
    const int m0  = (bid >> 4) * BT;
    const int n0  = (bid & 15) * BT;

    const __half* gpA = Aoh + (size_t)m0 * D_DIM;
    const __half* gpB = Bvh + (size_t)n0 * D_DIM;

    const int mat   = lid >> 3;
    const int mrow  = ((mat & 1) << 3) + (lid & 7);
    const int mcolb = (mat >> 1) << 4;

    float acc[MI][NI][4];
    #pragma unroll
    for (int i = 0; i < MI; i++)
        #pragma unroll
        for (int j = 0; j < NI; j++)
            #pragma unroll
            for (int q = 0; q < 4; q++) acc[i][j][q] = 0.f;

    auto issue = [&](int t) {
        const uint32_t sb = sbase + (t % STAGES) * STAGE_B;
        const int k0 = t * BKK;
        #pragma unroll
        for (int i = 0; i < CHK; i++) {
            const int c = tid + i * NT;
            const int r = c >> 3, cc = c & 7;
            cp_async16(sb + r * PITCH + cc * 16,
                       gpA + (size_t)r * D_DIM + k0 + cc * 8);
            cp_async16(sb + TPB + r * PITCH + cc * 16,
                       gpB + (size_t)r * D_DIM + k0 + cc * 8);
        }
    };

    #pragma unroll
    for (int t = 0; t < STAGES - 1; t++) {
        issue(t);
        asm volatile("cp.async.commit_group;" ::: "memory");
    }

    for (int t = 0; t < T; t++) {
        asm volatile("cp.async.wait_group %0;" :: "n"(STAGES - 2) : "memory");
        __syncthreads();
        if (t + STAGES - 1 < T) issue(t + STAGES - 1);
        asm volatile("cp.async.commit_group;" ::: "memory");

        const uint32_t bA = sbase + (t % STAGES) * STAGE_B;
        const uint32_t bB = bA + TPB;

        #pragma unroll
        for (int kk = 0; kk < BKK / 16; kk++) {
            uint32_t a0[MI][4];
            uint32_t b0[NI][2];
            #pragma unroll
            for (int mi = 0; mi < MI; mi++) {
                uint32_t roff = (uint32_t)(wm * WM + mi * 16 + mrow) * PITCH +
                                mcolb + kk * 32;
                ldmatrix_x4(a0[mi], bA + roff);
            }
            #pragma unroll
            for (int nj = 0; nj < NJ; nj++) {
                uint32_t roff = (uint32_t)(wn * WN + nj * 16 + mrow) * PITCH +
                                mcolb + kk * 32;
                uint32_t r[4];
                ldmatrix_x4(r, bB + roff);
                b0[nj * 2][0]     = r[0]; b0[nj * 2][1]     = r[2];
                b0[nj * 2 + 1][0] = r[1]; b0[nj * 2 + 1][1] = r[3];
            }
            #pragma unroll
            for (int mi = 0; mi < MI; mi++)
                #pragma unroll
                for (int ni = 0; ni < NI; ni++)
                    mma_f16(acc[mi][ni], a0[mi], b0[ni]);
        }
        __syncthreads();
    }

    const int trow = lid >> 2;
    const int tcol = (lid & 3) * 2;
    #pragma unroll
    for (int mi = 0; mi < MI; mi++) {
        const int row = m0 + wm * WM + mi * 16 + trow;
        #pragma unroll
        for (int ni = 0; ni < NI; ni++) {
            const int col = n0 + wn * WN + ni * 8 + tcol;
            #pragma unroll
            for (int h = 0; h < 2; h++) {
                const int rr = row + h * 8;
                __half2 hv(__float2half(acc[mi][ni][h * 2 + 0]),
                           __float2half(acc[mi][ni][h * 2 + 1]));
                *reinterpret_cast<__half2*>(&Whi[(size_t)rr * D_DIM + col]) = hv;
            }
        }
    }
}

// ------------------------- node 3: GEMM2 ----------------------------------
// out[m][n] = sum_k Vh[m,k] * Whi[n,k] + bias[n]
// CTA 128x128, 4 warps of 64x64, BK=64, 3-stage cp.async.
__global__ void __launch_bounds__(128, 2)
gemm2(const __half* __restrict__ A0, const __half* __restrict__ B0,
      float* __restrict__ C, const float* __restrict__ bias) {
    constexpr int BT = 128, WM = 64, WN = 64;
    constexpr int NWX = BT / WN;            // 2
    constexpr int MI = WM / 16, NI = WN / 8, NJ = WN / 16;
    constexpr int TPB = BT * PITCH;
    constexpr int STAGE_B = 2 * TPB;
    constexpr int STAGES = 3;
    constexpr int NT = 128;
    constexpr int CHK = (BT * 8) / NT;      // 8
    constexpr int T = D_DIM / BKK;          // 16

    extern __shared__ __align__(128) char smem[];
    const uint32_t sbase = smem_u32(smem);

    const int tid = threadIdx.x;
    const int wid = tid >> 5;
    const int lid = tid & 31;
    const int wm  = wid / NWX;
    const int wn  = wid % NWX;
    const int m0  = blockIdx.y * BT;
    const int n0  = blockIdx.x * BT;

    const __half* gpA = A0 + (size_t)m0 * D_DIM;
    const __half* gpB = B0 + (size_t)n0 * D_DIM;

    const int mat   = lid >> 3;
    const int mrow  = ((mat & 1) << 3) + (lid & 7);
    const int mcolb = (mat >> 1) << 4;

    float acc[MI][NI][4];
    #pragma unroll
    for (int i = 0; i < MI; i++)
        #pragma unroll
        for (int j = 0; j < NI; j++)
            #pragma unroll
            for (int q = 0; q < 4; q++) acc[i][j][q] = 0.f;

    auto issue = [&](int t) {
        const uint32_t sb = sbase + (t % STAGES) * STAGE_B;
        const int k0 = t * BKK;
        #pragma unroll
        for (int i = 0; i < CHK; i++) {
            const int c = tid + i * NT;
            const int r = c >> 3, cc = c & 7;
            cp_async16(sb + r * PITCH + cc * 16,
                       gpA + (size_t)r * D_DIM + k0 + cc * 8);
            cp_async16(sb + TPB + r * PITCH + cc * 16,
                       gpB + (size_t)r * D_DIM + k0 + cc * 8);
        }
    };

    #pragma unroll
    for (int t = 0; t < STAGES - 1; t++) {
        issue(t);
        asm volatile("cp.async.commit_group;" ::: "memory");
    }

    for (int t = 0; t < T; t++) {
        asm volatile("cp.async.wait_group %0;" :: "n"(STAGES - 2) : "memory");
        __syncthreads();
        if (t + STAGES - 1 < T) issue(t + STAGES - 1);
        asm volatile("cp.async.commit_group;" ::: "memory");

        const uint32_t bA = sbase + (t % STAGES) * STAGE_B;
        const uint32_t bB = bA + TPB;

        #pragma unroll
        for (int kk = 0; kk < BKK / 16; kk++) {
            uint32_t a0[MI][4];
            uint32_t b0[NI][2];
            #pragma unroll
            for (int mi = 0; mi < MI; mi++) {
                uint32_t roff = (uint32_t)(wm * WM + mi * 16 + mrow) * PITCH +
                                mcolb + kk * 32;
                ldmatrix_x4(a0[mi], bA + roff);
            }
            #pragma unroll
            for (int nj = 0; nj < NJ; nj++) {
                uint32_t roff = (uint32_t)(wn * WN + nj * 16 + mrow) * PITCH +
                                mcolb + kk * 32;
                uint32_t r[4];
                ldmatrix_x4(r, bB + roff);
                b0[nj * 2][0]     = r[0]; b0[nj * 2][1]     = r[2];
                b0[nj * 2 + 1][0] = r[1]; b0[nj * 2 + 1][1] = r[3];
            }
            #pragma unroll
            for (int mi = 0; mi < MI; mi++)
                #pragma unroll
                for (int ni = 0; ni < NI; ni++)
                    mma_f16(acc[mi][ni], a0[mi], b0[ni]);
        }
        __syncthreads();
    }

    const int trow = lid >> 2;
    const int tcol = (lid & 3) * 2;
    #pragma unroll
    for (int mi = 0; mi < MI; mi++) {
        const int row = m0 + wm * WM + mi * 16 + trow;
        #pragma unroll
        for (int ni = 0; ni < NI; ni++) {
            const int col = n0 + wn * WN + ni * 8 + tcol;
            float b0v = bias[col], b1v = bias[col + 1];
            float2 v0 = {acc[mi][ni][0] + b0v, acc[mi][ni][1] + b1v};
            float2 v1 = {acc[mi][ni][2] + b0v, acc[mi][ni][3] + b1v};
            *reinterpret_cast<float2*>(&C[(size_t)row * D_DIM + col]) = v0;
            *reinterpret_cast<float2*>(&C[(size_t)(row + 8) * D_DIM + col]) = v1;
        }
    }
}

// ------------------------- host launcher -------------------------
#define SMEM_G1 (3 * 2 * 64 * PITCH)    // 55296
#define SMEM_G2 (3 * 2 * 128 * PITCH)   // 110592

extern "C" void kernel_launch(void* const* d_in, const int* in_sizes, int n_in,
                              void* d_out, int out_size) {
    // 0 query, 1 key, 2 value, 3 mask, 4 Wq, 5 bq, 6 Wk, 7 bk, 8 Wv, 9 bv, 10 Wo, 11 bo
    const float* value = (const float*)d_in[2];
    const float* Wv    = (const float*)d_in[8];
    const float* bv    = (const float*)d_in[9];
    const float* Wo    = (const float*)d_in[10];
    const float* bo    = (const float*)d_in[11];
    float* out = (float*)d_out;

    void *pVh, *pAoh, *pBvh, *pWhi, *pbias;
    cudaGetSymbolAddress(&pVh, g_Vh);
    cudaGetSymbolAddress(&pAoh, g_Aoh);
    cudaGetSymbolAddress(&pBvh, g_Bvh);
    cudaGetSymbolAddress(&pWhi, g_Whi);
    cudaGetSymbolAddress(&pbias, g_bias);

    cudaFuncSetAttribute((const void*)gemm1_vconv,
                         cudaFuncAttributeMaxDynamicSharedMemorySize, SMEM_G1);
    cudaFuncSetAttribute((const void*)gemm2,
                         cudaFuncAttributeMaxDynamicSharedMemorySize, SMEM_G2);

    // 1) Wo->fp16 + bias GEMV, Wv transpose->fp16  (8 MB traffic)
    convert_wb<<<2048, 256>>>(Wo, bv, bo, Wv, (__half*)pAoh, (__half*)pBvh);

    // 2) GEMM1 (256 CTAs) + V convert (1024 CTAs) in one launch
    gemm1_vconv<<<1280, 128, SMEM_G1>>>(
        (const __half*)pAoh, (const __half*)pBvh, (__half*)pWhi,
        value, (uint32_t*)pVh);

    // 3) GEMM2: out = Vh @ Whi^T + bias
    {
        dim3 grid(D_DIM / 128, ROWS / 128);
        gemm2<<<grid, 128, SMEM_G2>>>(
            (const __half*)pVh, (const __half*)pWhi,
            out, (const float*)pbias);
    }
}